// round 1
// baseline (speedup 1.0000x reference)
#include <cuda_runtime.h>
#include <cstdint>

// ---------------------------------------------------------------------------
// _LSTMOneMany_3289944948986 : 2-layer GRU decoder with output feedback.
// B=512, IN=1024, H=2048, L=2, O=512, T=32.
//
// Structure per round:
//   h[l] = relu(x[:,l,:] @ embW^T + embB)                    (embedding GEMM)
//   2 warmup steps with zero input, then 31 feedback steps:
//     l0: gx0 = in @ Wih0^T ; gh0 = h0 @ Whh0^T  -> gates -> h0
//     l1: gx1 = h0 @ Wih1^T ; gh1 = h1 @ Whh1^T  -> gates -> h1
//     out = h1 @ outW^T + outB -> preds[:, t, :]
//
// GEMMs use tf32 mma.sync m16n8k8, 128x128x32 tiles, cp.async double buffer.
// ---------------------------------------------------------------------------

#define BSZ   512
#define HID   2048
#define OUTD  512
#define G3H   6144       // 3*H
#define GLD   12288      // 2*3H  (gx | gh packed)

// Scratch (allocation-free rule: __device__ globals)
__device__ float g_g [BSZ * GLD];    // [512][12288] packed gx|gh
__device__ float g_h0[BSZ * HID];
__device__ float g_h1[BSZ * HID];

// ---------------------------------------------------------------------------

__device__ __forceinline__ uint32_t f2tf(float f) {
    uint32_t u;
    asm("cvt.rna.tf32.f32 %0, %1;" : "=r"(u) : "f"(f));
    return u;
}

// tile [128 rows][32 cols] row-major; 16B-chunk XOR swizzle for conflict-free
// column-ish reads: physical chunk = chunk ^ (row & 7)
__device__ __forceinline__ int swz(int row, int col) {
    return row * 32 + ((((col >> 2) ^ row) & 7) << 2) + (col & 3);
}

// MODE 0: store raw C                       (gate pre-activations -> g buffer)
// MODE 1: C = acc + bias[n]                 (output projection -> preds slice)
// MODE 2: relu(acc + bias[n]) scattered to g_h0/g_h1 by row parity (embedding)
template <int MODE>
__global__ void __launch_bounds__(256)
gemm_tf32(const float* __restrict__ A0, int lda0,
          const float* __restrict__ B0, int ldb0, int K0,
          const float* __restrict__ A1, int lda1,
          const float* __restrict__ B1, int ldb1, int K1,
          int nSplit,
          float* __restrict__ C, int ldc,
          const float* __restrict__ bias)
{
    extern __shared__ float smem[];
    float* sA = smem;                 // [2][128*32]
    float* sB = smem + 2 * 128 * 32;  // [2][128*32]

    const int tid = threadIdx.x;
    const int bn  = blockIdx.x;
    const int bm  = blockIdx.y;
    const int nBase = bn * 128;

    const float* A; const float* B; int lda, ldb, K;
    if (nBase < nSplit) {
        A = A0; lda = lda0; B = B0 + (size_t)nBase * ldb0; ldb = ldb0; K = K0;
    } else {
        A = A1; lda = lda1; B = B1 + (size_t)(nBase - nSplit) * ldb1; ldb = ldb1; K = K1;
    }
    A += (size_t)bm * 128 * lda;

    const int tRow   = tid >> 3;   // 0..31
    const int tChunk = tid & 7;    // 0..7

    const int lane = tid & 31;
    const int warp = tid >> 5;
    const int wm = (warp >> 2) << 6;   // 0 / 64
    const int wn = (warp & 3) << 5;    // 0,32,64,96
    const int lr = lane >> 2;          // 0..7
    const int lc = lane & 3;           // 0..3

    float acc[4][4][4];
#pragma unroll
    for (int i = 0; i < 4; i++)
#pragma unroll
        for (int j = 0; j < 4; j++)
#pragma unroll
            for (int k = 0; k < 4; k++) acc[i][j][k] = 0.f;

    auto load_stage = [&](int s, int k0) {
#pragma unroll
        for (int p = 0; p < 4; p++) {
            int row = tRow + p * 32;
            int dst = s * 4096 + row * 32 + (((tChunk ^ row) & 7) << 2);
            const float* srcA = A + (size_t)row * lda + k0 + tChunk * 4;
            const float* srcB = B + (size_t)row * ldb + k0 + tChunk * 4;
            uint32_t da = (uint32_t)__cvta_generic_to_shared(&sA[dst]);
            uint32_t db = (uint32_t)__cvta_generic_to_shared(&sB[dst]);
            asm volatile("cp.async.cg.shared.global [%0], [%1], 16;\n" :: "r"(da), "l"(srcA));
            asm volatile("cp.async.cg.shared.global [%0], [%1], 16;\n" :: "r"(db), "l"(srcB));
        }
        asm volatile("cp.async.commit_group;\n");
    };

    const int nStages = K >> 5;
    load_stage(0, 0);
    int s = 0;

    for (int st = 0; st < nStages; st++) {
        if (st + 1 < nStages) {
            load_stage(s ^ 1, (st + 1) * 32);
            asm volatile("cp.async.wait_group 1;\n");
        } else {
            asm volatile("cp.async.wait_group 0;\n");
        }
        __syncthreads();

        const float* cA = sA + s * 4096;
        const float* cB = sB + s * 4096;

#pragma unroll
        for (int kk = 0; kk < 4; kk++) {
            const int k8 = kk * 8;
            uint32_t af[4][4], bf[4][2];
#pragma unroll
            for (int mt = 0; mt < 4; mt++) {
                int r = wm + mt * 16 + lr;
                af[mt][0] = f2tf(cA[swz(r,     k8 + lc)]);
                af[mt][1] = f2tf(cA[swz(r + 8, k8 + lc)]);
                af[mt][2] = f2tf(cA[swz(r,     k8 + lc + 4)]);
                af[mt][3] = f2tf(cA[swz(r + 8, k8 + lc + 4)]);
            }
#pragma unroll
            for (int nt = 0; nt < 4; nt++) {
                int r = wn + nt * 8 + lr;
                bf[nt][0] = f2tf(cB[swz(r, k8 + lc)]);
                bf[nt][1] = f2tf(cB[swz(r, k8 + lc + 4)]);
            }
#pragma unroll
            for (int mt = 0; mt < 4; mt++)
#pragma unroll
                for (int nt = 0; nt < 4; nt++) {
                    float* c = acc[mt][nt];
                    asm volatile(
                        "mma.sync.aligned.m16n8k8.row.col.f32.tf32.tf32.f32 "
                        "{%0,%1,%2,%3}, {%4,%5,%6,%7}, {%8,%9}, {%0,%1,%2,%3};\n"
                        : "+f"(c[0]), "+f"(c[1]), "+f"(c[2]), "+f"(c[3])
                        : "r"(af[mt][0]), "r"(af[mt][1]), "r"(af[mt][2]), "r"(af[mt][3]),
                          "r"(bf[nt][0]), "r"(bf[nt][1]));
                }
        }
        __syncthreads();
        s ^= 1;
    }

    // -------- epilogue --------
#pragma unroll
    for (int mt = 0; mt < 4; mt++)
#pragma unroll
        for (int nt = 0; nt < 4; nt++) {
            int m = bm * 128 + wm + mt * 16 + lr;
            int n = nBase + wn + nt * 8 + lc * 2;
            float2 v0 = make_float2(acc[mt][nt][0], acc[mt][nt][1]);
            float2 v1 = make_float2(acc[mt][nt][2], acc[mt][nt][3]);
            if (MODE == 0) {
                *(float2*)&C[(size_t)m       * ldc + n] = v0;
                *(float2*)&C[(size_t)(m + 8) * ldc + n] = v1;
            } else if (MODE == 1) {
                float b0 = bias[n], b1 = bias[n + 1];
                v0.x += b0; v0.y += b1; v1.x += b0; v1.y += b1;
                *(float2*)&C[(size_t)m       * ldc + n] = v0;
                *(float2*)&C[(size_t)(m + 8) * ldc + n] = v1;
            } else {  // MODE 2: embedding -> relu, scatter to h0/h1 by row parity
                float b0 = bias[n], b1 = bias[n + 1];
                v0.x = fmaxf(v0.x + b0, 0.f); v0.y = fmaxf(v0.y + b1, 0.f);
                v1.x = fmaxf(v1.x + b0, 0.f); v1.y = fmaxf(v1.y + b1, 0.f);
                float* dst = (m & 1) ? g_h1 : g_h0;
                int br = m >> 1;                 // rows m and m+8 share parity
                *(float2*)&dst[(size_t)br       * HID + n] = v0;
                *(float2*)&dst[(size_t)(br + 4) * HID + n] = v1;
            }
        }
}

// ---------------------------------------------------------------------------
// GRU gate epilogue:  r = sig(gx_r+gh_r); z = sig(gx_z+gh_z);
//                     n = tanh(gx_n + r*gh_n); h = (1-z)*n + z*h
// g layout: cols [0,6144) = gx (r|z|n), cols [6144,12288) = gh (r|z|n)
// hasGx==0: zero-input step, gx = bias only.
// ---------------------------------------------------------------------------
__global__ void __launch_bounds__(256)
gru_gates(const float* __restrict__ g,
          const float* __restrict__ bih, const float* __restrict__ bhh,
          float* __restrict__ h, int hasGx)
{
    int idx = blockIdx.x * 256 + threadIdx.x;   // < 512*2048
    int b = idx >> 11;
    int j = idx & 2047;
    const float* gb = g + (size_t)b * GLD;

    float gxr = bih[j], gxz = bih[HID + j], gxn = bih[2 * HID + j];
    if (hasGx) {
        gxr += gb[j];
        gxz += gb[HID + j];
        gxn += gb[2 * HID + j];
    }
    float ghr = gb[G3H + j]           + bhh[j];
    float ghz = gb[G3H + HID + j]     + bhh[HID + j];
    float ghn = gb[G3H + 2 * HID + j] + bhh[2 * HID + j];

    float r = 1.f / (1.f + expf(-(gxr + ghr)));
    float z = 1.f / (1.f + expf(-(gxz + ghz)));
    float n = tanhf(gxn + r * ghn);
    float hp = h[idx];
    h[idx] = (1.f - z) * n + z * hp;
}

// ---------------------------------------------------------------------------

static const int SMEM_BYTES = 4 * 128 * 32 * 4;   // 65536

static void launch_gemm(int mode, dim3 grid,
                        const float* A0, int lda0, const float* B0, int ldb0, int K0,
                        const float* A1, int lda1, const float* B1, int ldb1, int K1,
                        int nSplit, float* C, int ldc, const float* bias)
{
    switch (mode) {
    case 0:
        gemm_tf32<0><<<grid, 256, SMEM_BYTES>>>(A0, lda0, B0, ldb0, K0,
                                                A1, lda1, B1, ldb1, K1,
                                                nSplit, C, ldc, bias);
        break;
    case 1:
        gemm_tf32<1><<<grid, 256, SMEM_BYTES>>>(A0, lda0, B0, ldb0, K0,
                                                A1, lda1, B1, ldb1, K1,
                                                nSplit, C, ldc, bias);
        break;
    default:
        gemm_tf32<2><<<grid, 256, SMEM_BYTES>>>(A0, lda0, B0, ldb0, K0,
                                                A1, lda1, B1, ldb1, K1,
                                                nSplit, C, ldc, bias);
        break;
    }
}

extern "C" void kernel_launch(void* const* d_in, const int* in_sizes, int n_in,
                              void* d_out, int out_size)
{
    const float* x    = (const float*)d_in[0];   // [512, 2, 1024]
    const float* embW = (const float*)d_in[1];   // [2048, 1024]
    const float* embB = (const float*)d_in[2];   // [2048]
    const float* Wih0 = (const float*)d_in[3];   // [6144, 512]
    const float* Whh0 = (const float*)d_in[4];   // [6144, 2048]
    const float* bih0 = (const float*)d_in[5];
    const float* bhh0 = (const float*)d_in[6];
    const float* Wih1 = (const float*)d_in[7];   // [6144, 2048]
    const float* Whh1 = (const float*)d_in[8];   // [6144, 2048]
    const float* bih1 = (const float*)d_in[9];
    const float* bhh1 = (const float*)d_in[10];
    const float* outW = (const float*)d_in[11];  // [512, 2048]
    const float* outB = (const float*)d_in[12];
    float* out = (float*)d_out;                  // [512, 32, 512]

    cudaFuncSetAttribute((const void*)gemm_tf32<0>,
                         cudaFuncAttributeMaxDynamicSharedMemorySize, SMEM_BYTES);
    cudaFuncSetAttribute((const void*)gemm_tf32<1>,
                         cudaFuncAttributeMaxDynamicSharedMemorySize, SMEM_BYTES);
    cudaFuncSetAttribute((const void*)gemm_tf32<2>,
                         cudaFuncAttributeMaxDynamicSharedMemorySize, SMEM_BYTES);

    void* p;
    cudaGetSymbolAddress(&p, g_g);  float* g  = (float*)p;
    cudaGetSymbolAddress(&p, g_h0); float* h0 = (float*)p;
    cudaGetSymbolAddress(&p, g_h1); float* h1 = (float*)p;

    const int BIG = 1 << 30;
    const dim3 gGates(BSZ * HID / 256);

    // Embedding: M=1024 (b*2+l), N=2048, K=1024; relu; scatter to h0/h1.
    launch_gemm(2, dim3(2048 / 128, 1024 / 128),
                x, 1024, embW, 1024, 1024,
                x, 1024, embW, 1024, 1024,
                BIG, nullptr, 0, embB);

    // 2 warmup steps (zero input: gx0 GEMM skipped, gates use bias only).
    for (int w = 0; w < 2; w++) {
        launch_gemm(0, dim3(G3H / 128, BSZ / 128),               // gh0 only
                    h0, HID, Whh0, HID, HID,
                    h0, HID, Whh0, HID, HID,
                    BIG, g + G3H, GLD, nullptr);
        gru_gates<<<gGates, 256>>>(g, bih0, bhh0, h0, 0);

        launch_gemm(0, dim3(GLD / 128, BSZ / 128),               // gx1 | gh1
                    h0, HID, Wih1, HID, HID,
                    h1, HID, Whh1, HID, HID,
                    G3H, g, GLD, nullptr);
        gru_gates<<<gGates, 256>>>(g, bih1, bhh1, h1, 1);
    }

    // out0 -> preds[:, 0, :]
    launch_gemm(1, dim3(OUTD / 128, BSZ / 128),
                h1, HID, outW, HID, HID,
                h1, HID, outW, HID, HID,
                BIG, out, 32 * OUTD, outB);

    // Feedback steps t = 1..31
    for (int t = 1; t < 32; t++) {
        const float* prev = out + (size_t)(t - 1) * OUTD;        // preds[:, t-1, :]

        launch_gemm(0, dim3(GLD / 128, BSZ / 128),               // gx0 | gh0
                    prev, 32 * OUTD, Wih0, OUTD, OUTD,
                    h0, HID, Whh0, HID, HID,
                    G3H, g, GLD, nullptr);
        gru_gates<<<gGates, 256>>>(g, bih0, bhh0, h0, 1);

        launch_gemm(0, dim3(GLD / 128, BSZ / 128),               // gx1 | gh1
                    h0, HID, Wih1, HID, HID,
                    h1, HID, Whh1, HID, HID,
                    G3H, g, GLD, nullptr);
        gru_gates<<<gGates, 256>>>(g, bih1, bhh1, h1, 1);

        launch_gemm(1, dim3(OUTD / 128, BSZ / 128),              // out -> preds[:, t, :]
                    h1, HID, outW, HID, HID,
                    h1, HID, outW, HID, HID,
                    BIG, out + (size_t)t * OUTD, 32 * OUTD, outB);
    }
}

// round 5
// speedup vs baseline: 1.2044x; 1.2044x over previous
#include <cuda_runtime.h>
#include <cstdint>

// ---------------------------------------------------------------------------
// _LSTMOneMany_3289944948986 : 2-layer GRU decoder, B=512, H=2048, O=512, T=32.
// tf32 mma.sync GEMMs (tcgen05 unavailable: harness targets sm_103 family).
// Round 5 (resubmit of Round 3/4 after broker failures): pre-rounded tf32
// operands (no cvt in inner loop), 3-stage cp.async pipeline, 2 CTAs/SM,
// split-K output projection.
// ---------------------------------------------------------------------------

#define BSZ   512
#define HID   2048
#define OUTD  512
#define G3H   6144
#define GLD   12288
#define KSPLIT 8

// ---- scratch (__device__ globals; no allocation allowed) ----
__device__ __align__(16) float g_g   [BSZ * GLD];     // gate pre-activations
__device__ __align__(16) float g_h0  [BSZ * HID];     // exact fp32 state
__device__ __align__(16) float g_h1  [BSZ * HID];
__device__ __align__(16) float g_h0r [BSZ * HID];     // tf32-rounded GEMM copies
__device__ __align__(16) float g_h1r [BSZ * HID];
__device__ __align__(16) float g_outr[BSZ * OUTD];    // rounded feedback input
__device__ __align__(16) float g_part[KSPLIT * BSZ * OUTD];

// tf32-rounded weights / inputs
__device__ __align__(16) float w_x   [BSZ * 2 * 1024];
__device__ __align__(16) float w_emb [2048 * 1024];
__device__ __align__(16) float w_ih0 [G3H * OUTD];
__device__ __align__(16) float w_hh0 [G3H * HID];
__device__ __align__(16) float w_ih1 [G3H * HID];
__device__ __align__(16) float w_hh1 [G3H * HID];
__device__ __align__(16) float w_out [OUTD * HID];

// ---------------------------------------------------------------------------
__device__ __forceinline__ float roundtf(float x) {
    uint32_t u;
    asm("cvt.rna.tf32.f32 %0, %1;" : "=r"(u) : "f"(x));
    return __uint_as_float(u);
}

// smem tile [128 rows][32 cols] fp32; 16B-chunk XOR swizzle
__device__ __forceinline__ int swz(int row, int col) {
    return row * 32 + ((((col >> 2) ^ row) & 7) << 2) + (col & 3);
}

// ---------------------------------------------------------------------------
// GEMM: C[M,N] = A[M,K] @ B[N,K]^T, operands already tf32-rounded fp32.
// 128x128 CTA tile, 256 threads, 3-stage cp.async pipeline, 2 CTAs/SM.
// Per-N-block source select (nSplit) packs two GEMMs in one launch.
// MODE 0: raw store.  MODE 2: embedding (bias+relu, scatter h0/h1 + rounded).
// MODE 3: split-K partial (blockIdx.z slice of K) into g_part.
// ---------------------------------------------------------------------------
#define STAGE_FLTS (2 * 128 * 32)            // A+B per stage (floats)
static const int SMEM_BYTES = 3 * STAGE_FLTS * 4;   // 98304

template <int MODE>
__global__ void __launch_bounds__(256, 2)
gemm_tf32(const float* __restrict__ A0, int lda0,
          const float* __restrict__ B0, int ldb0, int K0,
          const float* __restrict__ A1, int lda1,
          const float* __restrict__ B1, int ldb1, int K1,
          int nSplit,
          float* __restrict__ C, int ldc,
          const float* __restrict__ bias)
{
    extern __shared__ float smem[];   // [3][A 128x32 | B 128x32]

    const int tid = threadIdx.x;
    const int bn  = blockIdx.x;
    const int bm  = blockIdx.y;
    const int nBase = bn * 128;

    const float* A; const float* B; int lda, ldb, K;
    if (nBase < nSplit) {
        A = A0; lda = lda0; B = B0 + (size_t)nBase * ldb0; ldb = ldb0; K = K0;
    } else {
        A = A1; lda = lda1; B = B1 + (size_t)(nBase - nSplit) * ldb1; ldb = ldb1; K = K1;
    }
    A += (size_t)bm * 128 * lda;
    if (MODE == 3) {
        int koff = blockIdx.z * K;
        A += koff; B += koff;
        C += (size_t)blockIdx.z * (BSZ * OUTD);
    }

    const int tRow   = tid >> 3;   // 0..31
    const int tChunk = tid & 7;    // 0..7

    const int lane = tid & 31;
    const int warp = tid >> 5;
    const int wm = (warp >> 2) << 6;   // 0 / 64
    const int wn = (warp & 3) << 5;    // 0,32,64,96
    const int lr = lane >> 2;          // 0..7
    const int lc = lane & 3;           // 0..3

    float acc[4][4][4];
#pragma unroll
    for (int i = 0; i < 4; i++)
#pragma unroll
        for (int j = 0; j < 4; j++)
#pragma unroll
            for (int k = 0; k < 4; k++) acc[i][j][k] = 0.f;

    auto load_stage = [&](int buf, int k0) {
        float* sA = smem + buf * STAGE_FLTS;
        float* sB = sA + 128 * 32;
#pragma unroll
        for (int p = 0; p < 4; p++) {
            int row = tRow + p * 32;
            int dst = row * 32 + (((tChunk ^ row) & 7) << 2);
            const float* srcA = A + (size_t)row * lda + k0 + tChunk * 4;
            const float* srcB = B + (size_t)row * ldb + k0 + tChunk * 4;
            uint32_t da = (uint32_t)__cvta_generic_to_shared(&sA[dst]);
            uint32_t db = (uint32_t)__cvta_generic_to_shared(&sB[dst]);
            asm volatile("cp.async.cg.shared.global [%0], [%1], 16;\n" :: "r"(da), "l"(srcA));
            asm volatile("cp.async.cg.shared.global [%0], [%1], 16;\n" :: "r"(db), "l"(srcB));
        }
        asm volatile("cp.async.commit_group;\n");
    };

    const int nStages = K >> 5;        // K is a multiple of 64 everywhere -> >= 2
    load_stage(0, 0);
    if (nStages > 1) load_stage(1, 32);
    int buf = 0;

    for (int st = 0; st < nStages; st++) {
        if (st + 2 < nStages) {
            load_stage((st + 2) % 3, (st + 2) * 32);
            asm volatile("cp.async.wait_group 2;\n");
        } else if (st + 1 < nStages) {
            asm volatile("cp.async.wait_group 1;\n");
        } else {
            asm volatile("cp.async.wait_group 0;\n");
        }
        __syncthreads();

        const uint32_t* cA = (const uint32_t*)(smem + buf * STAGE_FLTS);
        const uint32_t* cB = cA + 128 * 32;

#pragma unroll
        for (int kk = 0; kk < 4; kk++) {
            const int k8 = kk * 8;
            uint32_t af[4][4], bf[4][2];
#pragma unroll
            for (int mt = 0; mt < 4; mt++) {
                int r = wm + mt * 16 + lr;
                af[mt][0] = cA[swz(r,     k8 + lc)];
                af[mt][1] = cA[swz(r + 8, k8 + lc)];
                af[mt][2] = cA[swz(r,     k8 + lc + 4)];
                af[mt][3] = cA[swz(r + 8, k8 + lc + 4)];
            }
#pragma unroll
            for (int nt = 0; nt < 4; nt++) {
                int r = wn + nt * 8 + lr;
                bf[nt][0] = cB[swz(r, k8 + lc)];
                bf[nt][1] = cB[swz(r, k8 + lc + 4)];
            }
#pragma unroll
            for (int mt = 0; mt < 4; mt++)
#pragma unroll
                for (int nt = 0; nt < 4; nt++) {
                    float* c = acc[mt][nt];
                    asm volatile(
                        "mma.sync.aligned.m16n8k8.row.col.f32.tf32.tf32.f32 "
                        "{%0,%1,%2,%3}, {%4,%5,%6,%7}, {%8,%9}, {%0,%1,%2,%3};\n"
                        : "+f"(c[0]), "+f"(c[1]), "+f"(c[2]), "+f"(c[3])
                        : "r"(af[mt][0]), "r"(af[mt][1]), "r"(af[mt][2]), "r"(af[mt][3]),
                          "r"(bf[nt][0]), "r"(bf[nt][1]));
                }
        }
        __syncthreads();
        buf = (buf + 1) % 3;
    }

    // -------- epilogue --------
#pragma unroll
    for (int mt = 0; mt < 4; mt++)
#pragma unroll
        for (int nt = 0; nt < 4; nt++) {
            int m = bm * 128 + wm + mt * 16 + lr;
            int n = nBase + wn + nt * 8 + lc * 2;
            float2 v0 = make_float2(acc[mt][nt][0], acc[mt][nt][1]);
            float2 v1 = make_float2(acc[mt][nt][2], acc[mt][nt][3]);
            if (MODE == 0 || MODE == 3) {
                *(float2*)&C[(size_t)m       * ldc + n] = v0;
                *(float2*)&C[(size_t)(m + 8) * ldc + n] = v1;
            } else {  // MODE 2: embedding -> relu; scatter to h0/h1 (+ rounded)
                float b0 = bias[n], b1 = bias[n + 1];
                v0.x = fmaxf(v0.x + b0, 0.f); v0.y = fmaxf(v0.y + b1, 0.f);
                v1.x = fmaxf(v1.x + b0, 0.f); v1.y = fmaxf(v1.y + b1, 0.f);
                float* hp = (m & 1) ? g_h1  : g_h0;
                float* hr = (m & 1) ? g_h1r : g_h0r;
                size_t o0 = (size_t)(m >> 1) * HID + n;
                size_t o1 = o0 + 4 * HID;              // rows m, m+8 same parity
                *(float2*)&hp[o0] = v0;
                *(float2*)&hp[o1] = v1;
                *(float2*)&hr[o0] = make_float2(roundtf(v0.x), roundtf(v0.y));
                *(float2*)&hr[o1] = make_float2(roundtf(v1.x), roundtf(v1.y));
            }
        }
}

// ---------------------------------------------------------------------------
// GRU gates: r=sig(gx_r+gh_r), z=sig(gx_z+gh_z), n=tanh(gx_n+r*gh_n),
//            h = (1-z)*n + z*h.  Writes exact fp32 h + tf32-rounded copy.
// ---------------------------------------------------------------------------
__global__ void __launch_bounds__(256)
gru_gates(const float* __restrict__ g,
          const float* __restrict__ bih, const float* __restrict__ bhh,
          float* __restrict__ h, float* __restrict__ hr, int hasGx)
{
    int idx = blockIdx.x * 256 + threadIdx.x;   // < 512*2048
    int b = idx >> 11, j = idx & 2047;
    const float* gb = g + (size_t)b * GLD;

    float gxr = bih[j], gxz = bih[HID + j], gxn = bih[2 * HID + j];
    if (hasGx) { gxr += gb[j]; gxz += gb[HID + j]; gxn += gb[2 * HID + j]; }
    float ghr = gb[G3H + j]           + bhh[j];
    float ghz = gb[G3H + HID + j]     + bhh[HID + j];
    float ghn = gb[G3H + 2 * HID + j] + bhh[2 * HID + j];

    float r = 1.f / (1.f + expf(-(gxr + ghr)));
    float z = 1.f / (1.f + expf(-(gxz + ghz)));
    float n = tanhf(gxn + r * ghn);
    float hn = (1.f - z) * n + z * h[idx];
    h[idx]  = hn;
    hr[idx] = roundtf(hn);
}

// Reduce split-K partials + bias -> exact preds slice + rounded feedback buf.
__global__ void __launch_bounds__(256)
out_reduce(const float* __restrict__ outB, float* __restrict__ preds)
{
    int idx = blockIdx.x * 256 + threadIdx.x;   // < 512*512
    int o = idx & 511, b = idx >> 9;
    float v = outB[o];
#pragma unroll
    for (int z = 0; z < KSPLIT; z++) v += g_part[z * (BSZ * OUTD) + idx];
    preds[(size_t)b * (32 * OUTD) + o] = v;
    g_outr[idx] = roundtf(v);
}

// fp32 -> tf32-rounded fp32
__global__ void __launch_bounds__(256)
convR(const float* __restrict__ s, float* __restrict__ d, int n)
{
    int i = blockIdx.x * 256 + threadIdx.x;
    if (i < n) d[i] = roundtf(s[i]);
}

// ---------------------------------------------------------------------------

extern "C" void kernel_launch(void* const* d_in, const int* in_sizes, int n_in,
                              void* d_out, int out_size)
{
    const float* x    = (const float*)d_in[0];
    const float* embB = (const float*)d_in[2];
    const float* bih0 = (const float*)d_in[5];
    const float* bhh0 = (const float*)d_in[6];
    const float* bih1 = (const float*)d_in[9];
    const float* bhh1 = (const float*)d_in[10];
    const float* outB = (const float*)d_in[12];
    float* out = (float*)d_out;                  // [512, 32, 512]

    cudaFuncSetAttribute(gemm_tf32<0>,
                         cudaFuncAttributeMaxDynamicSharedMemorySize, SMEM_BYTES);
    cudaFuncSetAttribute(gemm_tf32<2>,
                         cudaFuncAttributeMaxDynamicSharedMemorySize, SMEM_BYTES);
    cudaFuncSetAttribute(gemm_tf32<3>,
                         cudaFuncAttributeMaxDynamicSharedMemorySize, SMEM_BYTES);

    void* p;
    cudaGetSymbolAddress(&p, g_g);    float* g    = (float*)p;
    cudaGetSymbolAddress(&p, g_h0);   float* h0   = (float*)p;
    cudaGetSymbolAddress(&p, g_h1);   float* h1   = (float*)p;
    cudaGetSymbolAddress(&p, g_h0r);  float* h0r  = (float*)p;
    cudaGetSymbolAddress(&p, g_h1r);  float* h1r  = (float*)p;
    cudaGetSymbolAddress(&p, g_outr); float* outr = (float*)p;
    cudaGetSymbolAddress(&p, g_part); float* part = (float*)p;
    cudaGetSymbolAddress(&p, w_x);    float* xr   = (float*)p;
    cudaGetSymbolAddress(&p, w_emb);  float* eW   = (float*)p;
    cudaGetSymbolAddress(&p, w_ih0);  float* i0   = (float*)p;
    cudaGetSymbolAddress(&p, w_hh0);  float* r0   = (float*)p;
    cudaGetSymbolAddress(&p, w_ih1);  float* i1   = (float*)p;
    cudaGetSymbolAddress(&p, w_hh1);  float* r1   = (float*)p;
    cudaGetSymbolAddress(&p, w_out);  float* oW   = (float*)p;

    auto conv = [](const float* s, float* d, int n) {
        convR<<<(n + 255) / 256, 256>>>(s, d, n);
    };
    conv(x,                      xr, BSZ * 2 * 1024);
    conv((const float*)d_in[1],  eW, 2048 * 1024);
    conv((const float*)d_in[3],  i0, G3H * OUTD);
    conv((const float*)d_in[4],  r0, G3H * HID);
    conv((const float*)d_in[7],  i1, G3H * HID);
    conv((const float*)d_in[8],  r1, G3H * HID);
    conv((const float*)d_in[11], oW, OUTD * HID);

    const int BIG = 1 << 30;
    const dim3 gGates(BSZ * HID / 256);

    // Embedding: M=1024 (b*2+l), N=2048, K=1024 -> relu -> h0/h1 + rounded
    gemm_tf32<2><<<dim3(2048 / 128, 1024 / 128), 256, SMEM_BYTES>>>(
        xr, 1024, eW, 1024, 1024,
        xr, 1024, eW, 1024, 1024,
        BIG, nullptr, 0, embB);

    // 2 warmup steps (zero input: gx0 skipped, gates use bias only)
    for (int w = 0; w < 2; w++) {
        gemm_tf32<0><<<dim3(G3H / 128, BSZ / 128), 256, SMEM_BYTES>>>(   // gh0
            h0r, HID, r0, HID, HID,
            h0r, HID, r0, HID, HID,
            BIG, g + G3H, GLD, nullptr);
        gru_gates<<<gGates, 256>>>(g, bih0, bhh0, h0, h0r, 0);

        gemm_tf32<0><<<dim3(GLD / 128, BSZ / 128), 256, SMEM_BYTES>>>(   // gx1|gh1
            h0r, HID, i1, HID, HID,
            h1r, HID, r1, HID, HID,
            G3H, g, GLD, nullptr);
        gru_gates<<<gGates, 256>>>(g, bih1, bhh1, h1, h1r, 1);
    }

    // out0 (split-K) -> preds[:,0,:] + rounded feedback
    gemm_tf32<3><<<dim3(OUTD / 128, BSZ / 128, KSPLIT), 256, SMEM_BYTES>>>(
        h1r, HID, oW, HID, HID / KSPLIT,
        h1r, HID, oW, HID, HID / KSPLIT,
        BIG, part, OUTD, nullptr);
    out_reduce<<<(BSZ * OUTD) / 256, 256>>>(outB, out);

    // Feedback steps t = 1..31
    for (int t = 1; t < 32; t++) {
        gemm_tf32<0><<<dim3(GLD / 128, BSZ / 128), 256, SMEM_BYTES>>>(   // gx0|gh0
            outr, OUTD, i0, OUTD, OUTD,
            h0r,  HID,  r0, HID,  HID,
            G3H, g, GLD, nullptr);
        gru_gates<<<gGates, 256>>>(g, bih0, bhh0, h0, h0r, 1);

        gemm_tf32<0><<<dim3(GLD / 128, BSZ / 128), 256, SMEM_BYTES>>>(   // gx1|gh1
            h0r, HID, i1, HID, HID,
            h1r, HID, r1, HID, HID,
            G3H, g, GLD, nullptr);
        gru_gates<<<gGates, 256>>>(g, bih1, bhh1, h1, h1r, 1);

        gemm_tf32<3><<<dim3(OUTD / 128, BSZ / 128, KSPLIT), 256, SMEM_BYTES>>>(
            h1r, HID, oW, HID, HID / KSPLIT,
            h1r, HID, oW, HID, HID / KSPLIT,
            BIG, part, OUTD, nullptr);
        out_reduce<<<(BSZ * OUTD) / 256, 256>>>(outB, out + (size_t)t * OUTD);
    }
}